// round 1
// baseline (speedup 1.0000x reference)
#include <cuda_runtime.h>
#include <math.h>

// ---------------- problem constants ----------------
#define BB 64
#define NN_TOK 1029
#define DD 768
#define HH 12
#define HD 64
#define KK 128
#define RR 5
#define MM 4
#define PP 1024              // N - R
#define CC 133               // R + K

// output layout: [out (B*N*D)] [cls_n (B*D)] [idx (B)]
#define OUT_CLS ((long)BB * NN_TOK * DD)
#define OUT_IDX (OUT_CLS + (long)BB * DD)

// ---------------- scratch (device globals; no allocs allowed) ----------------
__device__ int   g_idx[BB];
__device__ float g_scores[(long)BB * KK * PP];       // 33.5 MB (attn in-place)
__device__ float g_ctx[(long)BB * CC * DD];          // 26 MB
__device__ float g_kv[(long)BB * CC * 2 * DD];       // 52 MB
__device__ float g_q[(long)BB * NN_TOK * DD];        // 202 MB
__device__ float g_y[(long)BB * NN_TOK * DD];        // 202 MB

// ---------------- kernel 1: cls_n, sims, argmax ----------------
__global__ __launch_bounds__(256) void cls_kernel(
    const float* __restrict__ x, const float* __restrict__ cents,
    float* __restrict__ out_cls, float* __restrict__ out_idx, int* __restrict__ idx)
{
    int b = blockIdx.x;
    int t = threadIdx.x;
    __shared__ float red[256];
    __shared__ float snorm;
    __shared__ float best_s;
    __shared__ int best_i;

    const float* xr = x + (long)b * NN_TOK * DD;
    float loc[3];
    float ss = 0.f;
#pragma unroll
    for (int i = 0; i < 3; i++) { loc[i] = xr[t + i * 256]; ss += loc[i] * loc[i]; }
    red[t] = ss; __syncthreads();
    for (int s = 128; s > 0; s >>= 1) { if (t < s) red[t] += red[t + s]; __syncthreads(); }
    if (t == 0) snorm = fmaxf(sqrtf(red[0]), 1e-12f);
    __syncthreads();
    float inv = 1.0f / snorm;
    float c[3];
#pragma unroll
    for (int i = 0; i < 3; i++) {
        c[i] = loc[i] * inv;
        out_cls[(long)b * DD + t + i * 256] = c[i];
    }
    if (t == 0) { best_s = -1e30f; best_i = 0; }
    __syncthreads();
    for (int m = 0; m < MM; m++) {
        float p = 0.f;
#pragma unroll
        for (int i = 0; i < 3; i++) p += c[i] * cents[(long)m * DD + t + i * 256];
        red[t] = p; __syncthreads();
        for (int s = 128; s > 0; s >>= 1) { if (t < s) red[t] += red[t + s]; __syncthreads(); }
        if (t == 0) { if (red[0] > best_s) { best_s = red[0]; best_i = m; } }
        __syncthreads();
    }
    if (t == 0) { idx[b] = best_i; out_idx[b] = (float)best_i; }
}

// ---------------- SGEMM: 128x128x16 tile, 256 thr, 8x8/thread ----------------
// C[m,n] = sum_k A[m,k] * (TB ? B[n,k] : B[k,n]) (+ bias[n])
// N must be a multiple of 128 and Kd a multiple of 16 (true for all calls).
// Batched via blockIdx.z; A may be indexed through idxmap (Q_banks gather).
template<bool TB, bool BIAS>
__global__ __launch_bounds__(256) void sgemm(
    const float* __restrict__ Ab, const float* __restrict__ Bb,
    const float* __restrict__ bias, float* __restrict__ Cb,
    int M, int N, int Kd,
    long sA, long sB, long sC,
    const int* __restrict__ idxmap)
{
    __shared__ float As[16][132];
    __shared__ float Bs[16][132];

    int bz = blockIdx.z;
    const float* A  = Ab + (idxmap ? (long)idxmap[bz] * sA : (long)bz * sA);
    const float* Bm = Bb + (long)bz * sB;
    float* C        = Cb + (long)bz * sC;

    int m0 = blockIdx.y * 128;
    int n0 = blockIdx.x * 128;
    int tid = threadIdx.x;
    int tx = tid & 15, ty = tid >> 4;

    float acc[8][8];
#pragma unroll
    for (int i = 0; i < 8; i++)
#pragma unroll
        for (int j = 0; j < 8; j++) acc[i][j] = 0.f;

    for (int k0 = 0; k0 < Kd; k0 += 16) {
        // A tile: 128(m) x 16(k), stored transposed
#pragma unroll
        for (int it = 0; it < 2; it++) {
            int slot = tid + it * 256;
            int row = slot >> 2;
            int kc = (slot & 3) * 4;
            float4 v = make_float4(0.f, 0.f, 0.f, 0.f);
            int gr = m0 + row;
            if (gr < M) v = *reinterpret_cast<const float4*>(&A[(long)gr * Kd + k0 + kc]);
            As[kc + 0][row] = v.x; As[kc + 1][row] = v.y;
            As[kc + 2][row] = v.z; As[kc + 3][row] = v.w;
        }
        if (!TB) {
#pragma unroll
            for (int it = 0; it < 2; it++) {
                int slot = tid + it * 256;
                int kk = slot >> 5;
                int nc = (slot & 31) * 4;
                float4 v = *reinterpret_cast<const float4*>(&Bm[(long)(k0 + kk) * N + n0 + nc]);
                *reinterpret_cast<float4*>(&Bs[kk][nc]) = v;
            }
        } else {
#pragma unroll
            for (int it = 0; it < 2; it++) {
                int slot = tid + it * 256;
                int n = slot >> 2;
                int kc = (slot & 3) * 4;
                float4 v = *reinterpret_cast<const float4*>(&Bm[(long)(n0 + n) * Kd + k0 + kc]);
                Bs[kc + 0][n] = v.x; Bs[kc + 1][n] = v.y;
                Bs[kc + 2][n] = v.z; Bs[kc + 3][n] = v.w;
            }
        }
        __syncthreads();
#pragma unroll
        for (int kk = 0; kk < 16; kk++) {
            float a[8], b[8];
            *reinterpret_cast<float4*>(&a[0]) = *reinterpret_cast<float4*>(&As[kk][ty * 8]);
            *reinterpret_cast<float4*>(&a[4]) = *reinterpret_cast<float4*>(&As[kk][ty * 8 + 4]);
            *reinterpret_cast<float4*>(&b[0]) = *reinterpret_cast<float4*>(&Bs[kk][tx * 8]);
            *reinterpret_cast<float4*>(&b[4]) = *reinterpret_cast<float4*>(&Bs[kk][tx * 8 + 4]);
#pragma unroll
            for (int i = 0; i < 8; i++)
#pragma unroll
                for (int j = 0; j < 8; j++) acc[i][j] += a[i] * b[j];
        }
        __syncthreads();
    }

#pragma unroll
    for (int i = 0; i < 8; i++) {
        int gr = m0 + ty * 8 + i;
        if (gr >= M) continue;
#pragma unroll
        for (int j = 0; j < 8; j += 4) {
            int gc = n0 + tx * 8 + j;
            float4 v;
            v.x = acc[i][j];     v.y = acc[i][j + 1];
            v.z = acc[i][j + 2]; v.w = acc[i][j + 3];
            if (BIAS) { v.x += bias[gc]; v.y += bias[gc + 1]; v.z += bias[gc + 2]; v.w += bias[gc + 3]; }
            *reinterpret_cast<float4*>(&C[(long)gr * N + gc]) = v;
        }
    }
}

// ---------------- softmax over rows of length 1024 ----------------
__global__ __launch_bounds__(256) void softmax1024(float* __restrict__ s)
{
    long row = blockIdx.x;
    float* p = s + row * PP;
    int t = threadIdx.x;
    __shared__ float red[256];

    float4 v = reinterpret_cast<float4*>(p)[t];
    float mx = fmaxf(fmaxf(v.x, v.y), fmaxf(v.z, v.w));
    red[t] = mx; __syncthreads();
    for (int st = 128; st > 0; st >>= 1) { if (t < st) red[t] = fmaxf(red[t], red[t + st]); __syncthreads(); }
    mx = red[0]; __syncthreads();

    v.x = expf(v.x - mx); v.y = expf(v.y - mx);
    v.z = expf(v.z - mx); v.w = expf(v.w - mx);
    float sm = v.x + v.y + v.z + v.w;
    red[t] = sm; __syncthreads();
    for (int st = 128; st > 0; st >>= 1) { if (t < st) red[t] += red[t + st]; __syncthreads(); }
    float inv = 1.0f / red[0];
    v.x *= inv; v.y *= inv; v.z *= inv; v.w *= inv;
    reinterpret_cast<float4*>(p)[t] = v;
}

// ---------------- copy x[:, :R, :] into ctx rows 0..R-1 ----------------
__global__ __launch_bounds__(256) void copy_xreg(const float* __restrict__ x, float* __restrict__ ctx)
{
    long i = (long)blockIdx.x * blockDim.x + threadIdx.x; // float4 index
    long total = (long)BB * RR * DD / 4;
    if (i >= total) return;
    long per_b = (long)RR * DD / 4;
    long b = i / per_b;
    long r = i - b * per_b;
    reinterpret_cast<float4*>(ctx)[b * ((long)CC * DD / 4) + r] =
        reinterpret_cast<const float4*>(x)[b * ((long)NN_TOK * DD / 4) + r];
}

// ---------------- attention: one (b,h) per block, K/V in smem ----------------
__global__ __launch_bounds__(256) void attn_kernel(
    const float* __restrict__ q, const float* __restrict__ kv, float* __restrict__ y)
{
    extern __shared__ float sh[];
    float* sk = sh;              // [133][64]
    float* sv = sh + CC * HD;    // [133][64]
    int b = blockIdx.x / HH;
    int h = blockIdx.x % HH;
    int tid = threadIdx.x;

    for (int i = tid; i < CC * 16; i += 256) {   // float4 granularity
        int m = i >> 4;
        int jc = (i & 15) * 4;
        long base = ((long)(b * CC + m)) * (2 * DD) + h * HD + jc;
        *reinterpret_cast<float4*>(&sk[m * HD + jc]) = *reinterpret_cast<const float4*>(&kv[base]);
        *reinterpret_cast<float4*>(&sv[m * HD + jc]) = *reinterpret_cast<const float4*>(&kv[base + DD]);
    }
    __syncthreads();

    const float scale = 0.125f;  // 1/sqrt(64)
    for (int nb = 0; nb < NN_TOK; nb += 256) {
        int n = nb + tid;
        if (n >= NN_TOK) break;
        const float* qp = q + ((long)(b * NN_TOK + n)) * DD + h * HD;
        float qr[HD];
#pragma unroll
        for (int j = 0; j < HD; j += 4)
            *reinterpret_cast<float4*>(&qr[j]) = *reinterpret_cast<const float4*>(&qp[j]);

        float sbuf[CC];
        float mx = -1e30f;
        for (int m = 0; m < CC; m++) {
            const float* kp = &sk[m * HD];
            float s0 = 0.f, s1 = 0.f, s2 = 0.f, s3 = 0.f;
#pragma unroll
            for (int j = 0; j < HD; j += 4) {
                float4 kv4 = *reinterpret_cast<const float4*>(&kp[j]);
                s0 += qr[j] * kv4.x; s1 += qr[j + 1] * kv4.y;
                s2 += qr[j + 2] * kv4.z; s3 += qr[j + 3] * kv4.w;
            }
            float s = (s0 + s1) + (s2 + s3);
            sbuf[m] = s;
            mx = fmaxf(mx, s);
        }
        float acc[HD];
#pragma unroll
        for (int j = 0; j < HD; j++) acc[j] = 0.f;
        float ssum = 0.f;
        for (int m = 0; m < CC; m++) {
            float e = expf((sbuf[m] - mx) * scale);
            ssum += e;
            const float* vp = &sv[m * HD];
#pragma unroll
            for (int j = 0; j < HD; j += 4) {
                float4 vv = *reinterpret_cast<const float4*>(&vp[j]);
                acc[j] += e * vv.x; acc[j + 1] += e * vv.y;
                acc[j + 2] += e * vv.z; acc[j + 3] += e * vv.w;
            }
        }
        float inv = 1.0f / ssum;
        float* yp = y + ((long)(b * NN_TOK + n)) * DD + h * HD;
#pragma unroll
        for (int j = 0; j < HD; j += 4) {
            float4 o;
            o.x = acc[j] * inv; o.y = acc[j + 1] * inv;
            o.z = acc[j + 2] * inv; o.w = acc[j + 3] * inv;
            *reinterpret_cast<float4*>(&yp[j]) = o;
        }
    }
}

// ---------------- launch ----------------
extern "C" void kernel_launch(void* const* d_in, const int* in_sizes, int n_in,
                              void* d_out, int out_size)
{
    const float* x      = (const float*)d_in[0];
    const float* Qb     = (const float*)d_in[1];
    const float* Wq     = (const float*)d_in[2];
    const float* Wctx   = (const float*)d_in[3];
    const float* bctx   = (const float*)d_in[4];
    const float* Wout   = (const float*)d_in[5];
    const float* bout   = (const float*)d_in[6];
    const float* cents  = (const float*)d_in[7];
    float* out = (float*)d_out;

    void *p_idx, *p_scores, *p_ctx, *p_kv, *p_q, *p_y;
    cudaGetSymbolAddress(&p_idx, g_idx);
    cudaGetSymbolAddress(&p_scores, g_scores);
    cudaGetSymbolAddress(&p_ctx, g_ctx);
    cudaGetSymbolAddress(&p_kv, g_kv);
    cudaGetSymbolAddress(&p_q, g_q);
    cudaGetSymbolAddress(&p_y, g_y);
    int*   idxp = (int*)p_idx;
    float* scores = (float*)p_scores;
    float* ctx = (float*)p_ctx;
    float* kvp = (float*)p_kv;
    float* qp  = (float*)p_q;
    float* yp  = (float*)p_y;

    // 1. cls_n / idx
    cls_kernel<<<BB, 256>>>(x, cents, out + OUT_CLS, out + OUT_IDX, idxp);

    // 2. scores[b] = Q_banks[idx[b]] (128x768) @ xp[b]^T (1024x768)^T  -> (128,1024)
    sgemm<true, false><<<dim3(PP / 128, 1, BB), 256>>>(
        Qb, x + (long)RR * DD, nullptr, scores,
        KK, PP, DD,
        (long)KK * DD, (long)NN_TOK * DD, (long)KK * PP, idxp);

    // 3. softmax rows (B*K x 1024), in place
    softmax1024<<<BB * KK, 256>>>(scores);

    // 4. ctx[:, :R] = xreg
    {
        long total = (long)BB * RR * DD / 4;
        copy_xreg<<<(unsigned)((total + 255) / 256), 256>>>(x, ctx);
    }

    // 5. ctx[:, R:] = attn (128x1024) @ xp (1024x768)
    sgemm<false, false><<<dim3(DD / 128, 1, BB), 256>>>(
        scores, x + (long)RR * DD, nullptr, ctx + (long)RR * DD,
        KK, DD, PP,
        (long)KK * PP, (long)NN_TOK * DD, (long)CC * DD, nullptr);

    // 6. kv = ctx (8512x768) @ Wctx (768x1536) + bctx
    sgemm<false, true><<<dim3(1536 / 128, (BB * CC + 127) / 128, 1), 256>>>(
        ctx, Wctx, bctx, kvp,
        BB * CC, 2 * DD, DD, 0, 0, 0, nullptr);

    // 7. q = x (65856x768) @ Wq (768x768)
    sgemm<false, false><<<dim3(DD / 128, (BB * NN_TOK + 127) / 128, 1), 256>>>(
        x, Wq, nullptr, qp,
        BB * NN_TOK, DD, DD, 0, 0, 0, nullptr);

    // 8. attention -> y
    {
        int smem = CC * HD * 2 * (int)sizeof(float); // 68096 B
        cudaFuncSetAttribute(attn_kernel, cudaFuncAttributeMaxDynamicSharedMemorySize, smem);
        attn_kernel<<<BB * HH, 256, smem>>>(qp, kvp, yp);
    }

    // 9. out = y @ Wout + bout
    sgemm<false, true><<<dim3(DD / 128, (BB * NN_TOK + 127) / 128, 1), 256>>>(
        yp, Wout, bout, out,
        BB * NN_TOK, DD, DD, 0, 0, 0, nullptr);
}

// round 3
// speedup vs baseline: 1.6220x; 1.6220x over previous
#include <cuda_runtime.h>
#include <cuda_bf16.h>
#include <math.h>
#include <stdint.h>

// ---------------- problem constants ----------------
#define BB 64
#define NN_TOK 1029
#define DD 768
#define HH 12
#define HD 64
#define KK 128
#define RR 5
#define MM 4
#define PP 1024              // N - R
#define CC 133               // R + K

#define MPAD_X 65920         // 515*128  (>= B*N = 65856)
#define MPAD_C 8576          // 67*128   (>= B*C = 8512)

// output layout: [out (B*N*D)] [cls_n (B*D)] [idx (B)]
#define OUT_CLS ((long)BB * NN_TOK * DD)
#define OUT_IDX (OUT_CLS + (long)BB * DD)

// ---------------- scratch (device globals; no allocs allowed) ----------------
__device__ int   g_idx[BB];
__device__ float g_scores[(long)BB * KK * PP];
__device__ float g_ctx[(long)BB * CC * DD];
__device__ float g_kv[(long)BB * CC * 2 * DD];
__device__ float g_q[(long)BB * NN_TOK * DD];
__device__ float g_y[(long)BB * NN_TOK * DD];

// bf16 split buffers (zero-init covers padding rows)
__device__ __nv_bfloat16 g_x_hi[(long)MPAD_X * DD];
__device__ __nv_bfloat16 g_x_lo[(long)MPAD_X * DD];
__device__ __nv_bfloat16 g_y_hi[(long)MPAD_X * DD];
__device__ __nv_bfloat16 g_y_lo[(long)MPAD_X * DD];
__device__ __nv_bfloat16 g_c_hi[(long)MPAD_C * DD];
__device__ __nv_bfloat16 g_c_lo[(long)MPAD_C * DD];
__device__ __nv_bfloat16 g_qb_hi[(long)MM * KK * DD];
__device__ __nv_bfloat16 g_qb_lo[(long)MM * KK * DD];
__device__ __nv_bfloat16 g_wq_hi[DD * DD];
__device__ __nv_bfloat16 g_wq_lo[DD * DD];
__device__ __nv_bfloat16 g_wo_hi[DD * DD];
__device__ __nv_bfloat16 g_wo_lo[DD * DD];
__device__ __nv_bfloat16 g_wc_hi[2 * DD * DD];
__device__ __nv_bfloat16 g_wc_lo[2 * DD * DD];

// ---------------- PTX helpers ----------------
__device__ __forceinline__ uint32_t smem_u32(const void* p) {
    uint32_t a;
    asm("{ .reg .u64 t; cvta.to.shared.u64 t, %1; cvt.u32.u64 %0, t; }" : "=r"(a) : "l"(p));
    return a;
}
__device__ __forceinline__ void cpasync16(uint32_t dst, const void* src) {
    asm volatile("cp.async.cg.shared.global [%0], [%1], 16;" :: "r"(dst), "l"(src));
}
#define CP_COMMIT() asm volatile("cp.async.commit_group;" ::: "memory")
#define CP_WAIT1()  asm volatile("cp.async.wait_group 1;" ::: "memory")
#define CP_WAIT0()  asm volatile("cp.async.wait_group 0;" ::: "memory")

__device__ __forceinline__ void ldsm4(uint32_t* r, uint32_t addr) {
    asm volatile("ldmatrix.sync.aligned.m8n8.x4.shared.b16 {%0,%1,%2,%3}, [%4];"
        : "=r"(r[0]), "=r"(r[1]), "=r"(r[2]), "=r"(r[3]) : "r"(addr));
}
__device__ __forceinline__ void mma_bf16(float* c, const uint32_t* a, const uint32_t* b) {
    asm volatile(
        "mma.sync.aligned.m16n8k16.row.col.f32.bf16.bf16.f32 "
        "{%0,%1,%2,%3}, {%4,%5,%6,%7}, {%8,%9}, {%0,%1,%2,%3};"
        : "+f"(c[0]), "+f"(c[1]), "+f"(c[2]), "+f"(c[3])
        : "r"(a[0]), "r"(a[1]), "r"(a[2]), "r"(a[3]), "r"(b[0]), "r"(b[1]));
}

// ---------------- HMMA NT GEMM, fp32 via bf16 3-split ----------------
// C[m,n] (+= bias[n]) = sum_k A[m,k] * B[n,k]
// A: [Mpad, Kd] bf16 hi/lo row-major, B: [Ntot, Kd] bf16 hi/lo row-major
// Block tile 128x128, BK=32, 256 threads (8 warps: 4m x 2n, 32x64 each).
#define LDSB 80                    // smem bytes per tile row (32 bf16 + pad)
#define TILE_B (128 * LDSB)        // 10240
#define STAGE_B (4 * TILE_B)       // 40960
#define GEMM_SMEM (2 * STAGE_B)    // 81920

template<bool BIAS, bool GATHER>
__global__ void __launch_bounds__(256) gemm_mma(
    const __nv_bfloat16* __restrict__ Ahb, const __nv_bfloat16* __restrict__ Alb,
    const __nv_bfloat16* __restrict__ Bhb, const __nv_bfloat16* __restrict__ Blb,
    const float* __restrict__ bias, float* __restrict__ Cb,
    int M, int Ntot, int Kd,
    long sA, long sB, long sC,
    const int* __restrict__ idxmap)
{
    extern __shared__ char smem[];
    uint32_t sb = smem_u32(smem);

    int tid = threadIdx.x, wid = tid >> 5, lane = tid & 31;
    int warp_m = wid & 3, warp_n = wid >> 2;
    int bz = blockIdx.z;
    long aoff = GATHER ? (long)idxmap[bz] * sA : (long)bz * sA;
    const __nv_bfloat16* Ah = Ahb + aoff;
    const __nv_bfloat16* Al = Alb + aoff;
    const __nv_bfloat16* Bh = Bhb + (long)bz * sB;
    const __nv_bfloat16* Bl = Blb + (long)bz * sB;
    float* C = Cb + (long)bz * sC;

    int m0 = blockIdx.y * 128;
    int n0 = blockIdx.x * 128;

    float acc[2][8][4];
#pragma unroll
    for (int i = 0; i < 2; i++)
#pragma unroll
        for (int j = 0; j < 8; j++)
#pragma unroll
            for (int k = 0; k < 4; k++) acc[i][j][k] = 0.f;

    const int nch = Kd / 32;

    auto issue = [&](int ch) {
        uint32_t st = sb + (ch & 1) * STAGE_B;
        int k0 = ch * 32;
#pragma unroll
        for (int it = 0; it < 2; it++) {
            int idx = tid + it * 256;
            int r = idx >> 2, c = idx & 3;
            uint32_t so = r * LDSB + c * 16;
            long gA = (long)(m0 + r) * Kd + k0 + c * 8;
            long gB = (long)(n0 + r) * Kd + k0 + c * 8;
            cpasync16(st + so,              Ah + gA);
            cpasync16(st + TILE_B + so,     Al + gA);
            cpasync16(st + 2 * TILE_B + so, Bh + gB);
            cpasync16(st + 3 * TILE_B + so, Bl + gB);
        }
        CP_COMMIT();
    };

    issue(0);
    if (nch > 1) issue(1);

    int lr = lane & 15, lc = lane >> 4;

    for (int ch = 0; ch < nch; ch++) {
        if (ch < nch - 1) { CP_WAIT1(); } else { CP_WAIT0(); }
        __syncthreads();

        uint32_t stg = sb + (ch & 1) * STAGE_B;
        uint32_t Ah_s = stg;
        uint32_t Al_s = stg + TILE_B;
        uint32_t Bh_s = stg + 2 * TILE_B;
        uint32_t Bl_s = stg + 3 * TILE_B;

#pragma unroll
        for (int ks = 0; ks < 2; ks++) {
            uint32_t koff = ks * 32 + lc * 16;
            uint32_t ah[2][4], al[2][4], bh[8][2], bl[8][2];
#pragma unroll
            for (int mf = 0; mf < 2; mf++) {
                uint32_t row = warp_m * 32 + mf * 16 + lr;
                ldsm4(ah[mf], Ah_s + row * LDSB + koff);
                ldsm4(al[mf], Al_s + row * LDSB + koff);
            }
#pragma unroll
            for (int p = 0; p < 4; p++) {
                uint32_t row = warp_n * 64 + p * 16 + lr;
                uint32_t t[4];
                ldsm4(t, Bh_s + row * LDSB + koff);
                bh[2 * p][0] = t[0]; bh[2 * p][1] = t[2];
                bh[2 * p + 1][0] = t[1]; bh[2 * p + 1][1] = t[3];
                ldsm4(t, Bl_s + row * LDSB + koff);
                bl[2 * p][0] = t[0]; bl[2 * p][1] = t[2];
                bl[2 * p + 1][0] = t[1]; bl[2 * p + 1][1] = t[3];
            }
#pragma unroll
            for (int mf = 0; mf < 2; mf++)
#pragma unroll
                for (int nf = 0; nf < 8; nf++) {
                    mma_bf16(acc[mf][nf], ah[mf], bh[nf]);
                    mma_bf16(acc[mf][nf], ah[mf], bl[nf]);
                    mma_bf16(acc[mf][nf], al[mf], bh[nf]);
                }
        }
        __syncthreads();
        if (ch + 2 < nch) issue(ch + 2);
    }

    // epilogue
#pragma unroll
    for (int mf = 0; mf < 2; mf++) {
        int row0 = m0 + warp_m * 32 + mf * 16 + (lane >> 2);
#pragma unroll
        for (int nf = 0; nf < 8; nf++) {
            int col = n0 + warp_n * 64 + nf * 8 + (lane & 3) * 2;
            float b0 = 0.f, b1 = 0.f;
            if (BIAS) { b0 = bias[col]; b1 = bias[col + 1]; }
            if (row0 < M) {
                float2 v = make_float2(acc[mf][nf][0] + b0, acc[mf][nf][1] + b1);
                *reinterpret_cast<float2*>(&C[(long)row0 * Ntot + col]) = v;
            }
            if (row0 + 8 < M) {
                float2 v = make_float2(acc[mf][nf][2] + b0, acc[mf][nf][3] + b1);
                *reinterpret_cast<float2*>(&C[(long)(row0 + 8) * Ntot + col]) = v;
            }
        }
    }
}

// ---------------- split fp32 -> bf16 hi/lo (8 elems / thread) ----------------
__global__ __launch_bounds__(256) void split_kernel(
    const float4* __restrict__ in, uint4* __restrict__ hi, uint4* __restrict__ lo, long n8)
{
    long i = (long)blockIdx.x * 256 + threadIdx.x;
    if (i >= n8) return;
    float4 a = in[2 * i], b = in[2 * i + 1];
    float v[8] = { a.x, a.y, a.z, a.w, b.x, b.y, b.z, b.w };
    uint32_t hw[8], lw[8];
#pragma unroll
    for (int j = 0; j < 8; j++) {
        __nv_bfloat16 h = __float2bfloat16(v[j]);
        __nv_bfloat16 l = __float2bfloat16(v[j] - __bfloat162float(h));
        hw[j] = *reinterpret_cast<unsigned short*>(&h);
        lw[j] = *reinterpret_cast<unsigned short*>(&l);
    }
    uint4 H, L;
    H.x = hw[0] | (hw[1] << 16); H.y = hw[2] | (hw[3] << 16);
    H.z = hw[4] | (hw[5] << 16); H.w = hw[6] | (hw[7] << 16);
    L.x = lw[0] | (lw[1] << 16); L.y = lw[2] | (lw[3] << 16);
    L.z = lw[4] | (lw[5] << 16); L.w = lw[6] | (lw[7] << 16);
    hi[i] = H; lo[i] = L;
}

// ---------------- transpose + split weights: W[Kd,Nc] -> WT[Nc,Kd] ----------------
__global__ __launch_bounds__(256) void tsplit_kernel(
    const float* __restrict__ W, __nv_bfloat16* __restrict__ hiT,
    __nv_bfloat16* __restrict__ loT, int Kd, int Nc)
{
    int idx = blockIdx.x * 256 + threadIdx.x;
    if (idx >= Kd * Nc) return;
    int k = idx / Nc, n = idx % Nc;
    float a = W[idx];
    __nv_bfloat16 h = __float2bfloat16(a);
    __nv_bfloat16 l = __float2bfloat16(a - __bfloat162float(h));
    hiT[(long)n * Kd + k] = h;
    loT[(long)n * Kd + k] = l;
}

// ---------------- kernel 1: cls_n, sims, argmax ----------------
__global__ __launch_bounds__(256) void cls_kernel(
    const float* __restrict__ x, const float* __restrict__ cents,
    float* __restrict__ out_cls, float* __restrict__ out_idx, int* __restrict__ idx)
{
    int b = blockIdx.x;
    int t = threadIdx.x;
    __shared__ float red[256];
    __shared__ float snorm;
    __shared__ float best_s;
    __shared__ int best_i;

    const float* xr = x + (long)b * NN_TOK * DD;
    float loc[3];
    float ss = 0.f;
#pragma unroll
    for (int i = 0; i < 3; i++) { loc[i] = xr[t + i * 256]; ss += loc[i] * loc[i]; }
    red[t] = ss; __syncthreads();
    for (int s = 128; s > 0; s >>= 1) { if (t < s) red[t] += red[t + s]; __syncthreads(); }
    if (t == 0) snorm = fmaxf(sqrtf(red[0]), 1e-12f);
    __syncthreads();
    float inv = 1.0f / snorm;
    float c[3];
#pragma unroll
    for (int i = 0; i < 3; i++) {
        c[i] = loc[i] * inv;
        out_cls[(long)b * DD + t + i * 256] = c[i];
    }
    if (t == 0) { best_s = -1e30f; best_i = 0; }
    __syncthreads();
    for (int m = 0; m < MM; m++) {
        float p = 0.f;
#pragma unroll
        for (int i = 0; i < 3; i++) p += c[i] * cents[(long)m * DD + t + i * 256];
        red[t] = p; __syncthreads();
        for (int s = 128; s > 0; s >>= 1) { if (t < s) red[t] += red[t + s]; __syncthreads(); }
        if (t == 0) { if (red[0] > best_s) { best_s = red[0]; best_i = m; } }
        __syncthreads();
    }
    if (t == 0) { idx[b] = best_i; out_idx[b] = (float)best_i; }
}

// ---------------- SIMT SGEMM (kept for ctx_p) ----------------
template<bool TB, bool BIAS>
__global__ __launch_bounds__(256) void sgemm(
    const float* __restrict__ Ab, const float* __restrict__ Bb,
    const float* __restrict__ bias, float* __restrict__ Cb,
    int M, int N, int Kd,
    long sA, long sB, long sC,
    const int* __restrict__ idxmap)
{
    __shared__ float As[16][132];
    __shared__ float Bs[16][132];

    int bz = blockIdx.z;
    const float* A  = Ab + (idxmap ? (long)idxmap[bz] * sA : (long)bz * sA);
    const float* Bm = Bb + (long)bz * sB;
    float* C        = Cb + (long)bz * sC;

    int m0 = blockIdx.y * 128;
    int n0 = blockIdx.x * 128;
    int tid = threadIdx.x;
    int tx = tid & 15, ty = tid >> 4;

    float acc[8][8];
#pragma unroll
    for (int i = 0; i < 8; i++)
#pragma unroll
        for (int j = 0; j < 8; j++) acc[i][j] = 0.f;

    for (int k0 = 0; k0 < Kd; k0 += 16) {
#pragma unroll
        for (int it = 0; it < 2; it++) {
            int slot = tid + it * 256;
            int row = slot >> 2;
            int kc = (slot & 3) * 4;
            float4 v = make_float4(0.f, 0.f, 0.f, 0.f);
            int gr = m0 + row;
            if (gr < M) v = *reinterpret_cast<const float4*>(&A[(long)gr * Kd + k0 + kc]);
            As[kc + 0][row] = v.x; As[kc + 1][row] = v.y;
            As[kc + 2][row] = v.z; As[kc + 3][row] = v.w;
        }
        if (!TB) {
#pragma unroll
            for (int it = 0; it < 2; it++) {
                int slot = tid + it * 256;
                int kk = slot >> 5;
                int nc = (slot & 31) * 4;
                float4 v = *reinterpret_cast<const float4*>(&Bm[(long)(k0 + kk) * N + n0 + nc]);
                *reinterpret_cast<float4*>(&Bs[kk][nc]) = v;
            }
        } else {
#pragma unroll
            for (int it = 0; it < 2; it++) {
                int slot = tid + it * 256;
                int n = slot >> 2;
                int kc = (slot & 3) * 4;
                float4 v = *reinterpret_cast<const float4*>(&Bm[(long)(n0 + n) * Kd + k0 + kc]);
                Bs[kc + 0][n] = v.x; Bs[kc + 1][n] = v.y;
                Bs[kc + 2][n] = v.z; Bs[kc + 3][n] = v.w;
            }
        }
        __syncthreads();
#pragma unroll
        for (int kk = 0; kk < 16; kk++) {
            float a[8], b[8];
            *reinterpret_cast<float4*>(&a[0]) = *reinterpret_cast<float4*>(&As[kk][ty * 8]);
            *reinterpret_cast<float4*>(&a[4]) = *reinterpret_cast<float4*>(&As[kk][ty * 8 + 4]);
            *reinterpret_cast<float4*>(&b[0]) = *reinterpret_cast<float4*>(&Bs[kk][tx * 8]);
            *reinterpret_cast<float4*>(&b[4]) = *reinterpret_cast<float4*>(&Bs[kk][tx * 8 + 4]);
#pragma unroll
            for (int i = 0; i < 8; i++)
#pragma unroll
                for (int j = 0; j < 8; j++) acc[i][j] += a[i] * b[j];
        }
        __syncthreads();
    }

#pragma unroll
    for (int i = 0; i < 8; i++) {
        int gr = m0 + ty * 8 + i;
        if (gr >= M) continue;
#pragma unroll
        for (int j = 0; j < 8; j += 4) {
            int gc = n0 + tx * 8 + j;
            float4 v;
            v.x = acc[i][j];     v.y = acc[i][j + 1];
            v.z = acc[i][j + 2]; v.w = acc[i][j + 3];
            if (BIAS) { v.x += bias[gc]; v.y += bias[gc + 1]; v.z += bias[gc + 2]; v.w += bias[gc + 3]; }
            *reinterpret_cast<float4*>(&C[(long)gr * N + gc]) = v;
        }
    }
}

// ---------------- softmax over rows of length 1024 ----------------
__global__ __launch_bounds__(256) void softmax1024(float* __restrict__ s)
{
    long row = blockIdx.x;
    float* p = s + row * PP;
    int t = threadIdx.x;
    __shared__ float red[256];

    float4 v = reinterpret_cast<float4*>(p)[t];
    float mx = fmaxf(fmaxf(v.x, v.y), fmaxf(v.z, v.w));
    red[t] = mx; __syncthreads();
    for (int st = 128; st > 0; st >>= 1) { if (t < st) red[t] = fmaxf(red[t], red[t + st]); __syncthreads(); }
    mx = red[0]; __syncthreads();

    v.x = expf(v.x - mx); v.y = expf(v.y - mx);
    v.z = expf(v.z - mx); v.w = expf(v.w - mx);
    float sm = v.x + v.y + v.z + v.w;
    red[t] = sm; __syncthreads();
    for (int st = 128; st > 0; st >>= 1) { if (t < st) red[t] += red[t + st]; __syncthreads(); }
    float inv = 1.0f / red[0];
    v.x *= inv; v.y *= inv; v.z *= inv; v.w *= inv;
    reinterpret_cast<float4*>(p)[t] = v;
}

// ---------------- copy x[:, :R, :] into ctx rows 0..R-1 ----------------
__global__ __launch_bounds__(256) void copy_xreg(const float* __restrict__ x, float* __restrict__ ctx)
{
    long i = (long)blockIdx.x * blockDim.x + threadIdx.x;
    long total = (long)BB * RR * DD / 4;
    if (i >= total) return;
    long per_b = (long)RR * DD / 4;
    long b = i / per_b;
    long r = i - b * per_b;
    reinterpret_cast<float4*>(ctx)[b * ((long)CC * DD / 4) + r] =
        reinterpret_cast<const float4*>(x)[b * ((long)NN_TOK * DD / 4) + r];
}

// ---------------- attention: one (b,h) per block, K/V in smem ----------------
__global__ __launch_bounds__(256) void attn_kernel(
    const float* __restrict__ q, const float* __restrict__ kv, float* __restrict__ y)
{
    extern __shared__ float sh[];
    float* sk = sh;
    float* sv = sh + CC * HD;
    int b = blockIdx.x / HH;
    int h = blockIdx.x % HH;
    int tid = threadIdx.x;

    for (int i = tid; i < CC * 16; i += 256) {
        int m = i >> 4;
        int jc = (i & 15) * 4;
        long base = ((long)(b * CC + m)) * (2 * DD) + h * HD + jc;
        *reinterpret_cast<float4*>(&sk[m * HD + jc]) = *reinterpret_cast<const float4*>(&kv[base]);
        *reinterpret_cast<float4*>(&sv[m * HD + jc]) = *reinterpret_cast<const float4*>(&kv[base + DD]);
    }
    __syncthreads();

    const float scale = 0.125f;
    for (int nb = 0; nb < NN_TOK; nb += 256) {
        int n = nb + tid;
        if (n >= NN_TOK) break;
        const float* qp = q + ((long)(b * NN_TOK + n)) * DD + h * HD;
        float qr[HD];
#pragma unroll
        for (int j = 0; j < HD; j += 4)
            *reinterpret_cast<float4*>(&qr[j]) = *reinterpret_cast<const float4*>(&qp[j]);

        float sbuf[CC];
        float mx = -1e30f;
        for (int m = 0; m < CC; m++) {
            const float* kp = &sk[m * HD];
            float s0 = 0.f, s1 = 0.f, s2 = 0.f, s3 = 0.f;
#pragma unroll
            for (int j = 0; j < HD; j += 4) {
                float4 kv4 = *reinterpret_cast<const float4*>(&kp[j]);
                s0 += qr[j] * kv4.x; s1 += qr[j + 1] * kv4.y;
                s2 += qr[j + 2] * kv4.z; s3 += qr[j + 3] * kv4.w;
            }
            float s = (s0 + s1) + (s2 + s3);
            sbuf[m] = s;
            mx = fmaxf(mx, s);
        }
        float acc[HD];
#pragma unroll
        for (int j = 0; j < HD; j++) acc[j] = 0.f;
        float ssum = 0.f;
        for (int m = 0; m < CC; m++) {
            float e = expf((sbuf[m] - mx) * scale);
            ssum += e;
            const float* vp = &sv[m * HD];
#pragma unroll
            for (int j = 0; j < HD; j += 4) {
                float4 vv = *reinterpret_cast<const float4*>(&vp[j]);
                acc[j] += e * vv.x; acc[j + 1] += e * vv.y;
                acc[j + 2] += e * vv.z; acc[j + 3] += e * vv.w;
            }
        }
        float inv = 1.0f / ssum;
        float* yp = y + ((long)(b * NN_TOK + n)) * DD + h * HD;
#pragma unroll
        for (int j = 0; j < HD; j += 4) {
            float4 o;
            o.x = acc[j] * inv; o.y = acc[j + 1] * inv;
            o.z = acc[j + 2] * inv; o.w = acc[j + 3] * inv;
            *reinterpret_cast<float4*>(&yp[j]) = o;
        }
    }
}

// ---------------- launch ----------------
extern "C" void kernel_launch(void* const* d_in, const int* in_sizes, int n_in,
                              void* d_out, int out_size)
{
    const float* x      = (const float*)d_in[0];
    const float* Qb     = (const float*)d_in[1];
    const float* Wq     = (const float*)d_in[2];
    const float* Wctx   = (const float*)d_in[3];
    const float* bctx   = (const float*)d_in[4];
    const float* Wout   = (const float*)d_in[5];
    const float* bout   = (const float*)d_in[6];
    const float* cents  = (const float*)d_in[7];
    float* out = (float*)d_out;

    void *p_idx, *p_scores, *p_ctx, *p_kv, *p_q, *p_y;
    void *p_xh, *p_xl, *p_yh, *p_yl, *p_ch, *p_cl;
    void *p_qbh, *p_qbl, *p_wqh, *p_wql, *p_woh, *p_wol, *p_wch, *p_wcl;
    cudaGetSymbolAddress(&p_idx, g_idx);
    cudaGetSymbolAddress(&p_scores, g_scores);
    cudaGetSymbolAddress(&p_ctx, g_ctx);
    cudaGetSymbolAddress(&p_kv, g_kv);
    cudaGetSymbolAddress(&p_q, g_q);
    cudaGetSymbolAddress(&p_y, g_y);
    cudaGetSymbolAddress(&p_xh, g_x_hi);  cudaGetSymbolAddress(&p_xl, g_x_lo);
    cudaGetSymbolAddress(&p_yh, g_y_hi);  cudaGetSymbolAddress(&p_yl, g_y_lo);
    cudaGetSymbolAddress(&p_ch, g_c_hi);  cudaGetSymbolAddress(&p_cl, g_c_lo);
    cudaGetSymbolAddress(&p_qbh, g_qb_hi); cudaGetSymbolAddress(&p_qbl, g_qb_lo);
    cudaGetSymbolAddress(&p_wqh, g_wq_hi); cudaGetSymbolAddress(&p_wql, g_wq_lo);
    cudaGetSymbolAddress(&p_woh, g_wo_hi); cudaGetSymbolAddress(&p_wol, g_wo_lo);
    cudaGetSymbolAddress(&p_wch, g_wc_hi); cudaGetSymbolAddress(&p_wcl, g_wc_lo);

    int*   idxp   = (int*)p_idx;
    float* scores = (float*)p_scores;
    float* ctx    = (float*)p_ctx;
    float* kvp    = (float*)p_kv;
    float* qp     = (float*)p_q;
    float* yp     = (float*)p_y;
    __nv_bfloat16 *xh = (__nv_bfloat16*)p_xh, *xl = (__nv_bfloat16*)p_xl;
    __nv_bfloat16 *yh = (__nv_bfloat16*)p_yh, *yl = (__nv_bfloat16*)p_yl;
    __nv_bfloat16 *ch = (__nv_bfloat16*)p_ch, *cl = (__nv_bfloat16*)p_cl;
    __nv_bfloat16 *qbh = (__nv_bfloat16*)p_qbh, *qbl = (__nv_bfloat16*)p_qbl;
    __nv_bfloat16 *wqh = (__nv_bfloat16*)p_wqh, *wql = (__nv_bfloat16*)p_wql;
    __nv_bfloat16 *woh = (__nv_bfloat16*)p_woh, *wol = (__nv_bfloat16*)p_wol;
    __nv_bfloat16 *wch = (__nv_bfloat16*)p_wch, *wcl = (__nv_bfloat16*)p_wcl;

    cudaFuncSetAttribute(gemm_mma<false, false>, cudaFuncAttributeMaxDynamicSharedMemorySize, GEMM_SMEM);
    cudaFuncSetAttribute(gemm_mma<true, false>,  cudaFuncAttributeMaxDynamicSharedMemorySize, GEMM_SMEM);
    cudaFuncSetAttribute(gemm_mma<false, true>,  cudaFuncAttributeMaxDynamicSharedMemorySize, GEMM_SMEM);

    // 1. cls_n / idx
    cls_kernel<<<BB, 256>>>(x, cents, out + OUT_CLS, out + OUT_IDX, idxp);

    // 2. precision splits: x, Q_banks, weights (transposed)
    {
        long n8 = (long)BB * NN_TOK * DD / 8;
        split_kernel<<<(unsigned)((n8 + 255) / 256), 256>>>(
            (const float4*)x, (uint4*)xh, (uint4*)xl, n8);
        long q8 = (long)MM * KK * DD / 8;
        split_kernel<<<(unsigned)((q8 + 255) / 256), 256>>>(
            (const float4*)Qb, (uint4*)qbh, (uint4*)qbl, q8);
        tsplit_kernel<<<(DD * DD + 255) / 256, 256>>>(Wq, wqh, wql, DD, DD);
        tsplit_kernel<<<(DD * DD + 255) / 256, 256>>>(Wout, woh, wol, DD, DD);
        tsplit_kernel<<<(DD * 2 * DD + 255) / 256, 256>>>(Wctx, wch, wcl, DD, 2 * DD);
    }

    // 3. scores[b] = Q_banks[idx[b]] @ xp[b]^T  (128 x 1024, K=768) — HMMA
    gemm_mma<false, true><<<dim3(PP / 128, 1, BB), 256, GEMM_SMEM>>>(
        qbh, qbl, xh + (long)RR * DD, xl + (long)RR * DD, nullptr, scores,
        KK, PP, DD,
        (long)KK * DD, (long)NN_TOK * DD, (long)KK * PP, idxp);

    // 4. softmax rows (B*K x 1024), in place
    softmax1024<<<BB * KK, 256>>>(scores);

    // 5. ctx[:, :R] = xreg
    {
        long total = (long)BB * RR * DD / 4;
        copy_xreg<<<(unsigned)((total + 255) / 256), 256>>>(x, ctx);
    }

    // 6. ctx[:, R:] = attn (128x1024) @ xp (1024x768)  — SIMT fp32
    sgemm<false, false><<<dim3(DD / 128, 1, BB), 256>>>(
        scores, x + (long)RR * DD, nullptr, ctx + (long)RR * DD,
        KK, DD, PP,
        (long)KK * PP, (long)NN_TOK * DD, (long)CC * DD, nullptr);

    // 7. split ctx
    {
        long n8 = (long)BB * CC * DD / 8;
        split_kernel<<<(unsigned)((n8 + 255) / 256), 256>>>(
            (const float4*)ctx, (uint4*)ch, (uint4*)cl, n8);
    }

    // 8. kv = ctx (8512x768) @ Wctx + bctx — HMMA
    gemm_mma<true, false><<<dim3(2 * DD / 128, MPAD_C / 128, 1), 256, GEMM_SMEM>>>(
        ch, cl, wch, wcl, bctx, kvp,
        BB * CC, 2 * DD, DD, 0, 0, 0, nullptr);

    // 9. q = x (65856x768) @ Wq — HMMA
    gemm_mma<false, false><<<dim3(DD / 128, MPAD_X / 128, 1), 256, GEMM_SMEM>>>(
        xh, xl, wqh, wql, nullptr, qp,
        BB * NN_TOK, DD, DD, 0, 0, 0, nullptr);

    // 10. attention -> y (SIMT)
    {
        int smem = CC * HD * 2 * (int)sizeof(float);
        cudaFuncSetAttribute(attn_kernel, cudaFuncAttributeMaxDynamicSharedMemorySize, smem);
        attn_kernel<<<BB * HH, 256, smem>>>(qp, kvp, yp);
    }

    // 11. split y
    {
        long n8 = (long)BB * NN_TOK * DD / 8;
        split_kernel<<<(unsigned)((n8 + 255) / 256), 256>>>(
            (const float4*)yp, (uint4*)yh, (uint4*)yl, n8);
    }

    // 12. out = y @ Wout + bout — HMMA
    gemm_mma<true, false><<<dim3(DD / 128, MPAD_X / 128, 1), 256, GEMM_SMEM>>>(
        yh, yl, woh, wol, bout, out,
        BB * NN_TOK, DD, DD, 0, 0, 0, nullptr);
}